// round 3
// baseline (speedup 1.0000x reference)
#include <cuda_runtime.h>
#include <cuda_bf16.h>

// Problem constants
#define BT    4096      // B*T
#define CD    1024      // C
#define C3    3072      // 3C
#define TLEN  2048
#define NH    16
#define DH    64

// Scratch (allocation-free rule: device globals)
__device__ float g_qkv[BT * C3];   // 50.3 MB
__device__ float g_y[BT * CD];     // 16.8 MB

// ---------------------------------------------------------------------------
// SGEMM + bias:  Cmat[M,N] = A[M,K] @ B[K,N] + bias[N]
// 128x128 tile, BK=8, 256 threads, 8x8 per-thread microtile.
// Requires M%128==0, N%128==0, K%8==0 (true for all our shapes).
// ---------------------------------------------------------------------------
__global__ __launch_bounds__(256) void sgemm_bias(
    const float* __restrict__ A, const float* __restrict__ B,
    const float* __restrict__ bias, float* __restrict__ Cmat,
    int M, int N, int K)
{
    __shared__ float As[8][128];   // A transposed: As[k][m]
    __shared__ float Bs[8][128];

    const int tid = threadIdx.x;
    const int bm  = blockIdx.y * 128;
    const int bn  = blockIdx.x * 128;

    const int aRow = tid >> 1;          // 0..127
    const int aCol = (tid & 1) * 4;     // 0 or 4
    const int bRow = tid >> 5;          // 0..7
    const int bCol = (tid & 31) * 4;    // 0..124

    const int tm = (tid >> 4) * 8;      // 0..120
    const int tn = (tid & 15) * 8;      // 0..120

    const float* Aptr = A + (bm + aRow) * K + aCol;
    const float* Bptr = B + bRow * N + bn + bCol;

    float acc[8][8];
    #pragma unroll
    for (int i = 0; i < 8; i++)
        #pragma unroll
        for (int j = 0; j < 8; j++) acc[i][j] = 0.f;

    for (int k0 = 0; k0 < K; k0 += 8) {
        float4 a = *(const float4*)(Aptr + k0);
        float4 b = *(const float4*)(Bptr + k0 * N);
        __syncthreads();   // previous tile's compute done before overwrite
        As[aCol + 0][aRow] = a.x;
        As[aCol + 1][aRow] = a.y;
        As[aCol + 2][aRow] = a.z;
        As[aCol + 3][aRow] = a.w;
        *(float4*)&Bs[bRow][bCol] = b;
        __syncthreads();

        #pragma unroll
        for (int k = 0; k < 8; k++) {
            float ra[8], rb[8];
            *(float4*)(ra)     = *(const float4*)&As[k][tm];
            *(float4*)(ra + 4) = *(const float4*)&As[k][tm + 4];
            *(float4*)(rb)     = *(const float4*)&Bs[k][tn];
            *(float4*)(rb + 4) = *(const float4*)&Bs[k][tn + 4];
            #pragma unroll
            for (int i = 0; i < 8; i++)
                #pragma unroll
                for (int j = 0; j < 8; j++)
                    acc[i][j] += ra[i] * rb[j];
        }
    }

    float bb[8];
    #pragma unroll
    for (int j = 0; j < 8; j++) bb[j] = bias[bn + tn + j];

    #pragma unroll
    for (int i = 0; i < 8; i++) {
        float* crow = Cmat + (bm + tm + i) * N + bn + tn;
        float4 o0, o1;
        o0.x = acc[i][0] + bb[0]; o0.y = acc[i][1] + bb[1];
        o0.z = acc[i][2] + bb[2]; o0.w = acc[i][3] + bb[3];
        o1.x = acc[i][4] + bb[4]; o1.y = acc[i][5] + bb[5];
        o1.z = acc[i][6] + bb[6]; o1.w = acc[i][7] + bb[7];
        *(float4*)(crow)     = o0;
        *(float4*)(crow + 4) = o1;
    }
}

// ---------------------------------------------------------------------------
// Causal flash attention, fp32.
// Grid: (32 qtiles, 16 heads, 2 batch). 256 threads.
// Per CTA: 64 queries; stream over 64-key tiles with online softmax.
// Thread layout 16x16, each thread owns a 4(row)x4(col) fragment.
// Dynamic smem (51.2 KB): Qs[64][64], Kt[64][68] (K transposed; aliased by P
// after S is consumed), Vs[64][68].
// ---------------------------------------------------------------------------
__global__ __launch_bounds__(256) void attn_kernel(
    const float* __restrict__ qkv, float* __restrict__ y)
{
    extern __shared__ float sm[];
    float* Qs = sm;                    // 64*64
    float* Kt = sm + 64 * 64;          // 64*68  (also P after S consumed)
    float* Vs = Kt + 64 * 68;          // 64*68

    const int qt  = (int)gridDim.x - 1 - (int)blockIdx.x;  // heavy blocks first
    const int h   = blockIdx.y;
    const int b   = blockIdx.z;
    const int tid = threadIdx.x;
    const int ty  = tid >> 4;          // 0..15 -> rows 4*ty..4*ty+3
    const int tx  = tid & 15;          // 0..15 -> cols 4*tx..4*tx+3
    const int q0  = qt * 64;

    // Load Q tile (coalesced; first in-loop sync covers visibility)
    {
        const int qbase = (b * TLEN + q0) * C3 + h * DH;
        for (int idx = tid; idx < 64 * 64; idx += 256) {
            int t = idx >> 6, d = idx & 63;
            Qs[t * 64 + d] = qkv[qbase + t * C3 + d];
        }
    }

    float m_i[4], l_i[4], o[4][4];
    #pragma unroll
    for (int i = 0; i < 4; i++) {
        m_i[i] = -1e30f; l_i[i] = 0.f;
        #pragma unroll
        for (int j = 0; j < 4; j++) o[i][j] = 0.f;
    }

    const float scale = 0.125f;  // 1/sqrt(64)

    for (int kt = 0; kt <= qt; kt++) {
        const int k0    = kt * 64;
        const int kbase = (b * TLEN + k0) * C3 + CD + h * DH;
        const int vbase = kbase + CD;

        __syncthreads();  // previous iter finished reading Kt(P)/Vs
        for (int idx = tid; idx < 64 * 64; idx += 256) {
            int t = idx >> 6, d = idx & 63;
            Kt[d * 68 + t] = qkv[kbase + t * C3 + d];
            Vs[t * 68 + d] = qkv[vbase + t * C3 + d];
        }
        __syncthreads();

        // S = Q @ K^T  (4x4 fragment per thread)
        float s[4][4];
        #pragma unroll
        for (int i = 0; i < 4; i++)
            #pragma unroll
            for (int j = 0; j < 4; j++) s[i][j] = 0.f;

        #pragma unroll 8
        for (int d = 0; d < 64; d++) {
            float qv[4];
            #pragma unroll
            for (int i = 0; i < 4; i++) qv[i] = Qs[(4 * ty + i) * 64 + d];
            float4 kv = *(const float4*)&Kt[d * 68 + 4 * tx];
            #pragma unroll
            for (int i = 0; i < 4; i++) {
                s[i][0] += qv[i] * kv.x;
                s[i][1] += qv[i] * kv.y;
                s[i][2] += qv[i] * kv.z;
                s[i][3] += qv[i] * kv.w;
            }
        }

        // scale + causal mask (only diagonal tile is partial)
        const bool diag = (kt == qt);
        #pragma unroll
        for (int i = 0; i < 4; i++)
            #pragma unroll
            for (int j = 0; j < 4; j++) {
                float sv = s[i][j] * scale;
                if (diag && (k0 + 4 * tx + j > q0 + 4 * ty + i)) sv = -1e30f;
                s[i][j] = sv;
            }

        // online softmax: reductions across the 16 lanes sharing a row
        #pragma unroll
        for (int i = 0; i < 4; i++) {
            float mx = fmaxf(fmaxf(s[i][0], s[i][1]), fmaxf(s[i][2], s[i][3]));
            mx = fmaxf(mx, __shfl_xor_sync(0xffffffffu, mx, 1));
            mx = fmaxf(mx, __shfl_xor_sync(0xffffffffu, mx, 2));
            mx = fmaxf(mx, __shfl_xor_sync(0xffffffffu, mx, 4));
            mx = fmaxf(mx, __shfl_xor_sync(0xffffffffu, mx, 8));
            float mnew = fmaxf(m_i[i], mx);
            float corr = __expf(m_i[i] - mnew);
            m_i[i] = mnew;
            l_i[i] *= corr;
            #pragma unroll
            for (int j = 0; j < 4; j++) o[i][j] *= corr;

            float rs = 0.f;
            #pragma unroll
            for (int j = 0; j < 4; j++) {
                float p = __expf(s[i][j] - mnew);
                s[i][j] = p;
                rs += p;
            }
            rs += __shfl_xor_sync(0xffffffffu, rs, 1);
            rs += __shfl_xor_sync(0xffffffffu, rs, 2);
            rs += __shfl_xor_sync(0xffffffffu, rs, 4);
            rs += __shfl_xor_sync(0xffffffffu, rs, 8);
            l_i[i] += rs;
        }

        __syncthreads();  // all lanes done reading Kt before P overwrites it
        #pragma unroll
        for (int i = 0; i < 4; i++) {
            float4 p4 = make_float4(s[i][0], s[i][1], s[i][2], s[i][3]);
            *(float4*)&Kt[(4 * ty + i) * 68 + 4 * tx] = p4;
        }
        __syncthreads();

        // O += P @ V
        #pragma unroll 8
        for (int kk = 0; kk < 64; kk++) {
            float pv[4];
            #pragma unroll
            for (int i = 0; i < 4; i++) pv[i] = Kt[(4 * ty + i) * 68 + kk];
            float4 vv = *(const float4*)&Vs[kk * 68 + 4 * tx];
            #pragma unroll
            for (int i = 0; i < 4; i++) {
                o[i][0] += pv[i] * vv.x;
                o[i][1] += pv[i] * vv.y;
                o[i][2] += pv[i] * vv.z;
                o[i][3] += pv[i] * vv.w;
            }
        }
    }

    // epilogue: normalize and write y[b, q, h*64 + d]
    const int obase = (b * TLEN + q0) * CD + h * DH;
    #pragma unroll
    for (int i = 0; i < 4; i++) {
        float inv = 1.f / l_i[i];
        float4 r = make_float4(o[i][0] * inv, o[i][1] * inv,
                               o[i][2] * inv, o[i][3] * inv);
        *(float4*)&y[obase + (4 * ty + i) * CD + 4 * tx] = r;
    }
}

// ---------------------------------------------------------------------------
extern "C" void kernel_launch(void* const* d_in, const int* in_sizes, int n_in,
                              void* d_out, int out_size)
{
    const float* x      = (const float*)d_in[0];
    const float* W_attn = (const float*)d_in[1];
    const float* b_attn = (const float*)d_in[2];
    const float* W_proj = (const float*)d_in[3];
    const float* b_proj = (const float*)d_in[4];
    float* out = (float*)d_out;

    float *qkv = nullptr, *yb = nullptr;
    cudaGetSymbolAddress((void**)&qkv, g_qkv);
    cudaGetSymbolAddress((void**)&yb,  g_y);

    const int smem_attn = (64 * 64 + 2 * 64 * 68) * (int)sizeof(float);  // 51200
    cudaFuncSetAttribute(attn_kernel,
                         cudaFuncAttributeMaxDynamicSharedMemorySize, smem_attn);

    // 1) qkv = x @ W_attn + b_attn        [4096, 3072]
    dim3 g1(C3 / 128, BT / 128);
    sgemm_bias<<<g1, 256>>>(x, W_attn, b_attn, qkv, BT, C3, CD);

    // 2) causal flash attention -> y      [4096, 1024]
    dim3 g2(TLEN / 64, NH, 2);
    attn_kernel<<<g2, 256, smem_attn>>>(qkv, yb);

    // 3) out = y @ W_proj + b_proj        [4096, 1024]
    dim3 g3(CD / 128, BT / 128);
    sgemm_bias<<<g3, 256>>>(yb, W_proj, b_proj, out, BT, CD, CD);
}

// round 6
// speedup vs baseline: 1.5860x; 1.5860x over previous
#include <cuda_runtime.h>
#include <cuda_bf16.h>
#include <cstdint>

// Problem constants
#define BT    4096      // B*T
#define CD    1024      // C
#define C3    3072      // 3C
#define TLEN  2048
#define NH    16
#define DH    64

// Scratch (allocation-free rule: device globals)
__device__ float g_qkv[BT * C3];   // 50.3 MB
__device__ float g_y[BT * CD];     // 16.8 MB

// ---------------------------------------------------------------------------
// helpers
// ---------------------------------------------------------------------------
__device__ __forceinline__ uint32_t smem_u32(const void* p) {
    uint32_t a;
    asm("{ .reg .u64 t; cvta.to.shared.u64 t, %1; cvt.u32.u64 %0, t; }"
        : "=r"(a) : "l"(p));
    return a;
}

#define LDSM_X4(r0, r1, r2, r3, addr)                                          \
    asm volatile("ldmatrix.sync.aligned.m8n8.x4.shared.b16 {%0,%1,%2,%3}, [%4];" \
                 : "=r"(r0), "=r"(r1), "=r"(r2), "=r"(r3) : "r"(addr))

#define LDSM_X4_T(r0, r1, r2, r3, addr)                                        \
    asm volatile("ldmatrix.sync.aligned.m8n8.x4.trans.shared.b16 {%0,%1,%2,%3}, [%4];" \
                 : "=r"(r0), "=r"(r1), "=r"(r2), "=r"(r3) : "r"(addr))

__device__ __forceinline__ void mma_bf16(float* d, const uint32_t* a,
                                         const uint32_t* b) {
    asm volatile(
        "mma.sync.aligned.m16n8k16.row.col.f32.bf16.bf16.f32 "
        "{%0,%1,%2,%3}, {%4,%5,%6,%7}, {%8,%9}, {%0,%1,%2,%3};"
        : "+f"(d[0]), "+f"(d[1]), "+f"(d[2]), "+f"(d[3])
        : "r"(a[0]), "r"(a[1]), "r"(a[2]), "r"(a[3]), "r"(b[0]), "r"(b[1]));
}

// ---------------------------------------------------------------------------
// Split-bf16 HMMA GEMM + bias:  C[M,N] = A[M,K] @ W[K,N] + bias[N]
// grid (N/128, M/128), 256 threads. K % 32 == 0.
// hi/lo decomposition: x = hi + lo (bf16 each); C = aH*bH + aH*bL + aL*bH.
// ---------------------------------------------------------------------------
#define A_STRIDE 56     // halves; 112B rows: 16B-aligned, conflict-free ldmatrix
#define B_STRIDE 136    // halves; 272B rows: 16B-aligned, conflict-free ldmatrix.trans

__global__ __launch_bounds__(256, 2) void gemm_mma(
    const float* __restrict__ A, const float* __restrict__ W,
    const float* __restrict__ bias, float* __restrict__ C,
    int N, int K)
{
    __shared__ __align__(16) __nv_bfloat16 AsH[128][A_STRIDE];
    __shared__ __align__(16) __nv_bfloat16 AsL[128][A_STRIDE];
    __shared__ __align__(16) __nv_bfloat16 BsH[32][B_STRIDE];
    __shared__ __align__(16) __nv_bfloat16 BsL[32][B_STRIDE];

    const int tid  = threadIdx.x;
    const int wid  = tid >> 5;
    const int lane = tid & 31;
    const int bm   = blockIdx.y * 128;
    const int bn   = blockIdx.x * 128;
    const int wm   = (wid & 3) * 32;   // warp row base within CTA tile
    const int wn   = (wid >> 2) * 64;  // warp col base within CTA tile

    float acc[2][8][4];
    #pragma unroll
    for (int i = 0; i < 2; i++)
        #pragma unroll
        for (int j = 0; j < 8; j++)
            #pragma unroll
            for (int r = 0; r < 4; r++) acc[i][j][r] = 0.f;

    // precomputed ldmatrix smem addresses (byte offsets vary only by kk/mf/nf2)
    const uint32_t aH_base = smem_u32(&AsH[0][0]);
    const uint32_t aL_base = smem_u32(&AsL[0][0]);
    const uint32_t bH_base = smem_u32(&BsH[0][0]);
    const uint32_t bL_base = smem_u32(&BsL[0][0]);

    const int a_row = wm + (lane & 15);          // + mf*16
    const int a_col = (lane >> 4) * 8;           // + kk
    const int b_row = (lane & 7) + ((lane >> 3) & 1) * 8;  // + kk
    const int b_col = wn + (lane >> 4) * 8;      // + nf2*16

    for (int k0 = 0; k0 < K; k0 += 32) {
        __syncthreads();   // previous compute finished before overwrite

        // ---- A tile: 128m x 32k, split hi/lo ----
        #pragma unroll
        for (int i = 0; i < 4; i++) {
            int idx = tid + i * 256;
            int m = idx >> 3, f4 = idx & 7;
            float4 a = *(const float4*)(A + (size_t)(bm + m) * K + k0 + f4 * 4);
            __nv_bfloat162 h01 = __floats2bfloat162_rn(a.x, a.y);
            __nv_bfloat162 h23 = __floats2bfloat162_rn(a.z, a.w);
            float2 f01 = __bfloat1622float2(h01), f23 = __bfloat1622float2(h23);
            __nv_bfloat162 l01 = __floats2bfloat162_rn(a.x - f01.x, a.y - f01.y);
            __nv_bfloat162 l23 = __floats2bfloat162_rn(a.z - f23.x, a.w - f23.y);
            *(uint2*)&AsH[m][f4 * 4] =
                make_uint2(*(uint32_t*)&h01, *(uint32_t*)&h23);
            *(uint2*)&AsL[m][f4 * 4] =
                make_uint2(*(uint32_t*)&l01, *(uint32_t*)&l23);
        }

        // ---- B tile: 32k x 128n, split hi/lo ----
        #pragma unroll
        for (int i = 0; i < 4; i++) {
            int idx = tid + i * 256;
            int kr = idx >> 5, nf4 = idx & 31;
            float4 b = *(const float4*)(W + (size_t)(k0 + kr) * N + bn + nf4 * 4);
            __nv_bfloat162 h01 = __floats2bfloat162_rn(b.x, b.y);
            __nv_bfloat162 h23 = __floats2bfloat162_rn(b.z, b.w);
            float2 f01 = __bfloat1622float2(h01), f23 = __bfloat1622float2(h23);
            __nv_bfloat162 l01 = __floats2bfloat162_rn(b.x - f01.x, b.y - f01.y);
            __nv_bfloat162 l23 = __floats2bfloat162_rn(b.z - f23.x, b.w - f23.y);
            *(uint2*)&BsH[kr][nf4 * 4] =
                make_uint2(*(uint32_t*)&h01, *(uint32_t*)&h23);
            *(uint2*)&BsL[kr][nf4 * 4] =
                make_uint2(*(uint32_t*)&l01, *(uint32_t*)&l23);
        }
        __syncthreads();

        #pragma unroll
        for (int kk = 0; kk < 32; kk += 16) {
            uint32_t aH[2][4], aL[2][4];
            #pragma unroll
            for (int mf = 0; mf < 2; mf++) {
                uint32_t ah = aH_base +
                    ((a_row + mf * 16) * A_STRIDE + a_col + kk) * 2;
                uint32_t al = aL_base +
                    ((a_row + mf * 16) * A_STRIDE + a_col + kk) * 2;
                LDSM_X4(aH[mf][0], aH[mf][1], aH[mf][2], aH[mf][3], ah);
                LDSM_X4(aL[mf][0], aL[mf][1], aL[mf][2], aL[mf][3], al);
            }
            #pragma unroll
            for (int nf2 = 0; nf2 < 4; nf2++) {
                uint32_t bh = bH_base +
                    ((b_row + kk) * B_STRIDE + b_col + nf2 * 16) * 2;
                uint32_t bl = bL_base +
                    ((b_row + kk) * B_STRIDE + b_col + nf2 * 16) * 2;
                uint32_t bH[4], bL[4];
                LDSM_X4_T(bH[0], bH[1], bH[2], bH[3], bh);
                LDSM_X4_T(bL[0], bL[1], bL[2], bL[3], bl);
                #pragma unroll
                for (int mf = 0; mf < 2; mf++) {
                    #pragma unroll
                    for (int h = 0; h < 2; h++) {
                        float* d = acc[mf][nf2 * 2 + h];
                        mma_bf16(d, aH[mf], &bH[h * 2]);
                        mma_bf16(d, aH[mf], &bL[h * 2]);
                        mma_bf16(d, aL[mf], &bH[h * 2]);
                    }
                }
            }
        }
    }

    // ---- epilogue: fp32 acc + bias -> C ----
    const int rbase = bm + wm + (lane >> 2);
    const int cbase = bn + wn + (lane & 3) * 2;
    #pragma unroll
    for (int mf = 0; mf < 2; mf++) {
        #pragma unroll
        for (int nf = 0; nf < 8; nf++) {
            int col = cbase + nf * 8;
            float b0 = bias[col], b1 = bias[col + 1];
            int r0 = rbase + mf * 16;
            float2 v0 = make_float2(acc[mf][nf][0] + b0, acc[mf][nf][1] + b1);
            float2 v1 = make_float2(acc[mf][nf][2] + b0, acc[mf][nf][3] + b1);
            *(float2*)(C + (size_t)r0 * N + col)       = v0;
            *(float2*)(C + (size_t)(r0 + 8) * N + col) = v1;
        }
    }
}

// ---------------------------------------------------------------------------
// Causal flash attention, fp32 (known-good from R2)
// ---------------------------------------------------------------------------
__global__ __launch_bounds__(256) void attn_kernel(
    const float* __restrict__ qkv, float* __restrict__ y)
{
    extern __shared__ float smf[];
    float* Qs = smf;
    float* Kt = smf + 64 * 64;
    float* Vs = Kt + 64 * 68;

    const int qt  = (int)gridDim.x - 1 - (int)blockIdx.x;
    const int h   = blockIdx.y;
    const int b   = blockIdx.z;
    const int tid = threadIdx.x;
    const int ty  = tid >> 4;
    const int tx  = tid & 15;
    const int q0  = qt * 64;

    {
        const int qbase = (b * TLEN + q0) * C3 + h * DH;
        for (int idx = tid; idx < 64 * 64; idx += 256) {
            int t = idx >> 6, d = idx & 63;
            Qs[t * 64 + d] = qkv[qbase + t * C3 + d];
        }
    }

    float m_i[4], l_i[4], o[4][4];
    #pragma unroll
    for (int i = 0; i < 4; i++) {
        m_i[i] = -1e30f; l_i[i] = 0.f;
        #pragma unroll
        for (int j = 0; j < 4; j++) o[i][j] = 0.f;
    }

    const float scale = 0.125f;

    for (int kt = 0; kt <= qt; kt++) {
        const int k0    = kt * 64;
        const int kbase = (b * TLEN + k0) * C3 + CD + h * DH;
        const int vbase = kbase + CD;

        __syncthreads();
        for (int idx = tid; idx < 64 * 64; idx += 256) {
            int t = idx >> 6, d = idx & 63;
            Kt[d * 68 + t] = qkv[kbase + t * C3 + d];
            Vs[t * 68 + d] = qkv[vbase + t * C3 + d];
        }
        __syncthreads();

        float s[4][4];
        #pragma unroll
        for (int i = 0; i < 4; i++)
            #pragma unroll
            for (int j = 0; j < 4; j++) s[i][j] = 0.f;

        #pragma unroll 8
        for (int d = 0; d < 64; d++) {
            float qv[4];
            #pragma unroll
            for (int i = 0; i < 4; i++) qv[i] = Qs[(4 * ty + i) * 64 + d];
            float4 kv = *(const float4*)&Kt[d * 68 + 4 * tx];
            #pragma unroll
            for (int i = 0; i < 4; i++) {
                s[i][0] += qv[i] * kv.x;
                s[i][1] += qv[i] * kv.y;
                s[i][2] += qv[i] * kv.z;
                s[i][3] += qv[i] * kv.w;
            }
        }

        const bool diag = (kt == qt);
        #pragma unroll
        for (int i = 0; i < 4; i++)
            #pragma unroll
            for (int j = 0; j < 4; j++) {
                float sv = s[i][j] * scale;
                if (diag && (k0 + 4 * tx + j > q0 + 4 * ty + i)) sv = -1e30f;
                s[i][j] = sv;
            }

        #pragma unroll
        for (int i = 0; i < 4; i++) {
            float mx = fmaxf(fmaxf(s[i][0], s[i][1]), fmaxf(s[i][2], s[i][3]));
            mx = fmaxf(mx, __shfl_xor_sync(0xffffffffu, mx, 1));
            mx = fmaxf(mx, __shfl_xor_sync(0xffffffffu, mx, 2));
            mx = fmaxf(mx, __shfl_xor_sync(0xffffffffu, mx, 4));
            mx = fmaxf(mx, __shfl_xor_sync(0xffffffffu, mx, 8));
            float mnew = fmaxf(m_i[i], mx);
            float corr = __expf(m_i[i] - mnew);
            m_i[i] = mnew;
            l_i[i] *= corr;
            #pragma unroll
            for (int j = 0; j < 4; j++) o[i][j] *= corr;

            float rs = 0.f;
            #pragma unroll
            for (int j = 0; j < 4; j++) {
                float p = __expf(s[i][j] - mnew);
                s[i][j] = p;
                rs += p;
            }
            rs += __shfl_xor_sync(0xffffffffu, rs, 1);
            rs += __shfl_xor_sync(0xffffffffu, rs, 2);
            rs += __shfl_xor_sync(0xffffffffu, rs, 4);
            rs += __shfl_xor_sync(0xffffffffu, rs, 8);
            l_i[i] += rs;
        }

        __syncthreads();
        #pragma unroll
        for (int i = 0; i < 4; i++) {
            float4 p4 = make_float4(s[i][0], s[i][1], s[i][2], s[i][3]);
            *(float4*)&Kt[(4 * ty + i) * 68 + 4 * tx] = p4;
        }
        __syncthreads();

        #pragma unroll 8
        for (int kk = 0; kk < 64; kk++) {
            float pv[4];
            #pragma unroll
            for (int i = 0; i < 4; i++) pv[i] = Kt[(4 * ty + i) * 68 + kk];
            float4 vv = *(const float4*)&Vs[kk * 68 + 4 * tx];
            #pragma unroll
            for (int i = 0; i < 4; i++) {
                o[i][0] += pv[i] * vv.x;
                o[i][1] += pv[i] * vv.y;
                o[i][2] += pv[i] * vv.z;
                o[i][3] += pv[i] * vv.w;
            }
        }
    }

    const int obase = (b * TLEN + q0) * CD + h * DH;
    #pragma unroll
    for (int i = 0; i < 4; i++) {
        float inv = 1.f / l_i[i];
        float4 r = make_float4(o[i][0] * inv, o[i][1] * inv,
                               o[i][2] * inv, o[i][3] * inv);
        *(float4*)&y[obase + (4 * ty + i) * CD + 4 * tx] = r;
    }
}

// ---------------------------------------------------------------------------
extern "C" void kernel_launch(void* const* d_in, const int* in_sizes, int n_in,
                              void* d_out, int out_size)
{
    const float* x      = (const float*)d_in[0];
    const float* W_attn = (const float*)d_in[1];
    const float* b_attn = (const float*)d_in[2];
    const float* W_proj = (const float*)d_in[3];
    const float* b_proj = (const float*)d_in[4];
    float* out = (float*)d_out;

    float *qkv = nullptr, *yb = nullptr;
    cudaGetSymbolAddress((void**)&qkv, g_qkv);
    cudaGetSymbolAddress((void**)&yb,  g_y);

    const int smem_attn = (64 * 64 + 2 * 64 * 68) * (int)sizeof(float);  // 51200
    cudaFuncSetAttribute(attn_kernel,
                         cudaFuncAttributeMaxDynamicSharedMemorySize, smem_attn);

    // 1) qkv = x @ W_attn + b_attn   [4096, 3072]
    dim3 g1(C3 / 128, BT / 128);
    gemm_mma<<<g1, 256>>>(x, W_attn, b_attn, qkv, C3, CD);

    // 2) causal flash attention -> y [4096, 1024]
    dim3 g2(TLEN / 64, NH, 2);
    attn_kernel<<<g2, 256, smem_attn>>>(qkv, yb);

    // 3) out = y @ W_proj + b_proj   [4096, 1024]
    dim3 g3(CD / 128, BT / 128);
    gemm_mma<<<g3, 256>>>(yb, W_proj, b_proj, out, CD, CD);
}

// round 7
// speedup vs baseline: 2.8473x; 1.7953x over previous
#include <cuda_runtime.h>
#include <cuda_bf16.h>
#include <cstdint>

// Problem constants
#define BT    4096      // B*T
#define CD    1024      // C
#define C3    3072      // 3C
#define TLEN  2048
#define NH    16
#define DH    64

// Scratch (allocation-free rule: device globals)
__device__ float g_qkv[BT * C3];   // 50.3 MB
__device__ float g_y[BT * CD];     // 16.8 MB

// ---------------------------------------------------------------------------
// helpers
// ---------------------------------------------------------------------------
__device__ __forceinline__ uint32_t smem_u32(const void* p) {
    uint32_t a;
    asm("{ .reg .u64 t; cvta.to.shared.u64 t, %1; cvt.u32.u64 %0, t; }"
        : "=r"(a) : "l"(p));
    return a;
}

#define LDSM_X4(r0, r1, r2, r3, addr)                                          \
    asm volatile("ldmatrix.sync.aligned.m8n8.x4.shared.b16 {%0,%1,%2,%3}, [%4];" \
                 : "=r"(r0), "=r"(r1), "=r"(r2), "=r"(r3) : "r"(addr))

#define LDSM_X4_T(r0, r1, r2, r3, addr)                                        \
    asm volatile("ldmatrix.sync.aligned.m8n8.x4.trans.shared.b16 {%0,%1,%2,%3}, [%4];" \
                 : "=r"(r0), "=r"(r1), "=r"(r2), "=r"(r3) : "r"(addr))

__device__ __forceinline__ void mma_bf16(float* d, const uint32_t* a,
                                         const uint32_t* b) {
    asm volatile(
        "mma.sync.aligned.m16n8k16.row.col.f32.bf16.bf16.f32 "
        "{%0,%1,%2,%3}, {%4,%5,%6,%7}, {%8,%9}, {%0,%1,%2,%3};"
        : "+f"(d[0]), "+f"(d[1]), "+f"(d[2]), "+f"(d[3])
        : "r"(a[0]), "r"(a[1]), "r"(a[2]), "r"(a[3]), "r"(b[0]), "r"(b[1]));
}

// split fp32x4 -> bf16 hi + bf16 lo residual, store 8B each
__device__ __forceinline__ void split_store4(float4 v, void* H, void* L) {
    __nv_bfloat162 h01 = __floats2bfloat162_rn(v.x, v.y);
    __nv_bfloat162 h23 = __floats2bfloat162_rn(v.z, v.w);
    float2 f01 = __bfloat1622float2(h01), f23 = __bfloat1622float2(h23);
    __nv_bfloat162 l01 = __floats2bfloat162_rn(v.x - f01.x, v.y - f01.y);
    __nv_bfloat162 l23 = __floats2bfloat162_rn(v.z - f23.x, v.w - f23.y);
    *(uint2*)H = make_uint2(*(uint32_t*)&h01, *(uint32_t*)&h23);
    *(uint2*)L = make_uint2(*(uint32_t*)&l01, *(uint32_t*)&l23);
}

// ---------------------------------------------------------------------------
// Split-bf16 HMMA GEMM + bias (known-good from R5)
// ---------------------------------------------------------------------------
#define A_STRIDE 56
#define B_STRIDE 136

__global__ __launch_bounds__(256, 2) void gemm_mma(
    const float* __restrict__ A, const float* __restrict__ W,
    const float* __restrict__ bias, float* __restrict__ C,
    int N, int K)
{
    __shared__ __align__(16) __nv_bfloat16 AsH[128][A_STRIDE];
    __shared__ __align__(16) __nv_bfloat16 AsL[128][A_STRIDE];
    __shared__ __align__(16) __nv_bfloat16 BsH[32][B_STRIDE];
    __shared__ __align__(16) __nv_bfloat16 BsL[32][B_STRIDE];

    const int tid  = threadIdx.x;
    const int wid  = tid >> 5;
    const int lane = tid & 31;
    const int bm   = blockIdx.y * 128;
    const int bn   = blockIdx.x * 128;
    const int wm   = (wid & 3) * 32;
    const int wn   = (wid >> 2) * 64;

    float acc[2][8][4];
    #pragma unroll
    for (int i = 0; i < 2; i++)
        #pragma unroll
        for (int j = 0; j < 8; j++)
            #pragma unroll
            for (int r = 0; r < 4; r++) acc[i][j][r] = 0.f;

    const uint32_t aH_base = smem_u32(&AsH[0][0]);
    const uint32_t aL_base = smem_u32(&AsL[0][0]);
    const uint32_t bH_base = smem_u32(&BsH[0][0]);
    const uint32_t bL_base = smem_u32(&BsL[0][0]);

    const int a_row = wm + (lane & 15);
    const int a_col = (lane >> 4) * 8;
    const int b_row = (lane & 7) + ((lane >> 3) & 1) * 8;
    const int b_col = wn + (lane >> 4) * 8;

    for (int k0 = 0; k0 < K; k0 += 32) {
        __syncthreads();

        #pragma unroll
        for (int i = 0; i < 4; i++) {
            int idx = tid + i * 256;
            int m = idx >> 3, f4 = idx & 7;
            float4 a = *(const float4*)(A + (size_t)(bm + m) * K + k0 + f4 * 4);
            split_store4(a, &AsH[m][f4 * 4], &AsL[m][f4 * 4]);
        }
        #pragma unroll
        for (int i = 0; i < 4; i++) {
            int idx = tid + i * 256;
            int kr = idx >> 5, nf4 = idx & 31;
            float4 b = *(const float4*)(W + (size_t)(k0 + kr) * N + bn + nf4 * 4);
            split_store4(b, &BsH[kr][nf4 * 4], &BsL[kr][nf4 * 4]);
        }
        __syncthreads();

        #pragma unroll
        for (int kk = 0; kk < 32; kk += 16) {
            uint32_t aH[2][4], aL[2][4];
            #pragma unroll
            for (int mf = 0; mf < 2; mf++) {
                uint32_t ah = aH_base +
                    ((a_row + mf * 16) * A_STRIDE + a_col + kk) * 2;
                uint32_t al = aL_base +
                    ((a_row + mf * 16) * A_STRIDE + a_col + kk) * 2;
                LDSM_X4(aH[mf][0], aH[mf][1], aH[mf][2], aH[mf][3], ah);
                LDSM_X4(aL[mf][0], aL[mf][1], aL[mf][2], aL[mf][3], al);
            }
            #pragma unroll
            for (int nf2 = 0; nf2 < 4; nf2++) {
                uint32_t bh = bH_base +
                    ((b_row + kk) * B_STRIDE + b_col + nf2 * 16) * 2;
                uint32_t bl = bL_base +
                    ((b_row + kk) * B_STRIDE + b_col + nf2 * 16) * 2;
                uint32_t bH[4], bL[4];
                LDSM_X4_T(bH[0], bH[1], bH[2], bH[3], bh);
                LDSM_X4_T(bL[0], bL[1], bL[2], bL[3], bl);
                #pragma unroll
                for (int mf = 0; mf < 2; mf++) {
                    #pragma unroll
                    for (int h = 0; h < 2; h++) {
                        float* d = acc[mf][nf2 * 2 + h];
                        mma_bf16(d, aH[mf], &bH[h * 2]);
                        mma_bf16(d, aH[mf], &bL[h * 2]);
                        mma_bf16(d, aL[mf], &bH[h * 2]);
                    }
                }
            }
        }
    }

    const int rbase = bm + wm + (lane >> 2);
    const int cbase = bn + wn + (lane & 3) * 2;
    #pragma unroll
    for (int mf = 0; mf < 2; mf++) {
        #pragma unroll
        for (int nf = 0; nf < 8; nf++) {
            int col = cbase + nf * 8;
            float b0 = bias[col], b1 = bias[col + 1];
            int r0 = rbase + mf * 16;
            float2 v0 = make_float2(acc[mf][nf][0] + b0, acc[mf][nf][1] + b1);
            float2 v1 = make_float2(acc[mf][nf][2] + b0, acc[mf][nf][3] + b1);
            *(float2*)(C + (size_t)r0 * N + col)       = v0;
            *(float2*)(C + (size_t)(r0 + 8) * N + col) = v1;
        }
    }
}

// ---------------------------------------------------------------------------
// Causal flash attention with split-bf16 mma.sync.
// Grid (32 qtiles, 16 heads, 2 batch), 128 threads (4 warps x 16 q-rows).
// smem: Q/K/V hi+lo, [64][72] bf16 each (54 KB dynamic).
// S = Q K^T: A = Q (ldmatrix), B = K[key][d] via NON-trans ldmatrix (= col-major frag).
// P stays in registers (C-frag layout == A-frag layout), split hi/lo for PV.
// ---------------------------------------------------------------------------
#define AT_STRIDE 72

__global__ __launch_bounds__(128) void attn_mma(
    const float* __restrict__ qkv, float* __restrict__ y)
{
    extern __shared__ __nv_bfloat16 smb[];
    __nv_bfloat16* Qh = smb;
    __nv_bfloat16* Ql = Qh + 64 * AT_STRIDE;
    __nv_bfloat16* Kh = Ql + 64 * AT_STRIDE;
    __nv_bfloat16* Kl = Kh + 64 * AT_STRIDE;
    __nv_bfloat16* Vh = Kl + 64 * AT_STRIDE;
    __nv_bfloat16* Vl = Vh + 64 * AT_STRIDE;

    const int qt   = (int)gridDim.x - 1 - (int)blockIdx.x;  // heavy first
    const int h    = blockIdx.y;
    const int b    = blockIdx.z;
    const int tid  = threadIdx.x;
    const int wid  = tid >> 5;
    const int lane = tid & 31;
    const int q0   = qt * 64;
    const int wq   = wid * 16;

    const uint32_t Qh_b = smem_u32(Qh), Ql_b = smem_u32(Ql);
    const uint32_t Kh_b = smem_u32(Kh), Kl_b = smem_u32(Kl);
    const uint32_t Vh_b = smem_u32(Vh), Vl_b = smem_u32(Vl);

    // ---- load + split Q tile [64][64] ----
    {
        const size_t qbase = (size_t)(b * TLEN + q0) * C3 + h * DH;
        #pragma unroll
        for (int i = 0; i < 8; i++) {
            int idx = tid + i * 128;
            int r = idx >> 4, c4 = idx & 15;
            float4 v = *(const float4*)(qkv + qbase + (size_t)r * C3 + c4 * 4);
            split_store4(v, &Qh[r * AT_STRIDE + c4 * 4], &Ql[r * AT_STRIDE + c4 * 4]);
        }
    }

    float m_i[2] = {-1e30f, -1e30f}, l_i[2] = {0.f, 0.f};
    float ofrag[8][4];
    #pragma unroll
    for (int nt = 0; nt < 8; nt++)
        #pragma unroll
        for (int r = 0; r < 4; r++) ofrag[nt][r] = 0.f;

    // ldmatrix address components
    const int qa_row = wq + (lane & 15);
    const int qa_col = (lane >> 4) * 8;
    const int kb_row = ((lane >> 4) << 3) + (lane & 7);   // + np*16
    const int kb_col = ((lane >> 3) & 1) * 8;             // + ks*16
    const int vb_row = (lane & 7) + ((lane >> 3) & 1) * 8; // + ks*16
    const int vb_col = (lane >> 4) * 8;                    // + np*16

    for (int kt = 0; kt <= qt; kt++) {
        const size_t kbase = (size_t)(b * TLEN + kt * 64) * C3 + CD + h * DH;
        const size_t vbase = kbase + CD;

        __syncthreads();   // prev iter's PV reads done
        #pragma unroll
        for (int i = 0; i < 8; i++) {
            int idx = tid + i * 128;
            int r = idx >> 4, c4 = idx & 15;
            float4 kv = *(const float4*)(qkv + kbase + (size_t)r * C3 + c4 * 4);
            split_store4(kv, &Kh[r * AT_STRIDE + c4 * 4], &Kl[r * AT_STRIDE + c4 * 4]);
            float4 vv = *(const float4*)(qkv + vbase + (size_t)r * C3 + c4 * 4);
            split_store4(vv, &Vh[r * AT_STRIDE + c4 * 4], &Vl[r * AT_STRIDE + c4 * 4]);
        }
        __syncthreads();

        // ---- S = Q K^T ----
        float sfrag[8][4];
        #pragma unroll
        for (int nt = 0; nt < 8; nt++)
            #pragma unroll
            for (int r = 0; r < 4; r++) sfrag[nt][r] = 0.f;

        #pragma unroll
        for (int ks = 0; ks < 4; ks++) {
            uint32_t qh[4], ql[4];
            uint32_t qa = (qa_row * AT_STRIDE + ks * 16 + qa_col) * 2;
            LDSM_X4(qh[0], qh[1], qh[2], qh[3], Qh_b + qa);
            LDSM_X4(ql[0], ql[1], ql[2], ql[3], Ql_b + qa);
            #pragma unroll
            for (int np = 0; np < 4; np++) {
                uint32_t ka = ((np * 16 + kb_row) * AT_STRIDE + ks * 16 + kb_col) * 2;
                uint32_t kh[4], kl[4];
                LDSM_X4(kh[0], kh[1], kh[2], kh[3], Kh_b + ka);
                LDSM_X4(kl[0], kl[1], kl[2], kl[3], Kl_b + ka);
                mma_bf16(sfrag[2*np],   qh, &kh[0]);
                mma_bf16(sfrag[2*np],   qh, &kl[0]);
                mma_bf16(sfrag[2*np],   ql, &kh[0]);
                mma_bf16(sfrag[2*np+1], qh, &kh[2]);
                mma_bf16(sfrag[2*np+1], qh, &kl[2]);
                mma_bf16(sfrag[2*np+1], ql, &kh[2]);
            }
        }

        // ---- scale + causal mask ----
        const bool diag = (kt == qt);
        #pragma unroll
        for (int nt = 0; nt < 8; nt++) {
            #pragma unroll
            for (int r = 0; r < 4; r++) {
                float sv = sfrag[nt][r] * 0.125f;
                if (diag) {
                    int col = nt * 8 + (lane & 3) * 2 + (r & 1);
                    int row = wq + (lane >> 2) + (r >> 1) * 8;
                    if (col > row) sv = -1e30f;
                }
                sfrag[nt][r] = sv;
            }
        }

        // ---- online softmax (rows owned by 4-lane groups) ----
        #pragma unroll
        for (int r = 0; r < 2; r++) {
            float mx = -1e30f;
            #pragma unroll
            for (int nt = 0; nt < 8; nt++)
                mx = fmaxf(mx, fmaxf(sfrag[nt][2*r], sfrag[nt][2*r+1]));
            mx = fmaxf(mx, __shfl_xor_sync(0xffffffffu, mx, 1));
            mx = fmaxf(mx, __shfl_xor_sync(0xffffffffu, mx, 2));
            float mnew = fmaxf(m_i[r], mx);
            float corr = __expf(m_i[r] - mnew);
            m_i[r] = mnew;
            float rs = 0.f;
            #pragma unroll
            for (int nt = 0; nt < 8; nt++) {
                float p0 = __expf(sfrag[nt][2*r]   - mnew);
                float p1 = __expf(sfrag[nt][2*r+1] - mnew);
                sfrag[nt][2*r] = p0; sfrag[nt][2*r+1] = p1;
                rs += p0 + p1;
            }
            rs += __shfl_xor_sync(0xffffffffu, rs, 1);
            rs += __shfl_xor_sync(0xffffffffu, rs, 2);
            l_i[r] = l_i[r] * corr + rs;
            #pragma unroll
            for (int nt = 0; nt < 8; nt++) {
                ofrag[nt][2*r]   *= corr;
                ofrag[nt][2*r+1] *= corr;
            }
        }

        // ---- O += P V (P packed from registers, split hi/lo) ----
        #pragma unroll
        for (int ks = 0; ks < 4; ks++) {
            const float* s0 = sfrag[2*ks];
            const float* s1 = sfrag[2*ks+1];
            uint32_t pH[4], pL[4];
            #pragma unroll
            for (int q = 0; q < 4; q++) {
                const float* sp = (q < 2) ? s0 : s1;
                float x0 = sp[(q & 1) * 2], x1 = sp[(q & 1) * 2 + 1];
                __nv_bfloat162 hh = __floats2bfloat162_rn(x0, x1);
                float2 ff = __bfloat1622float2(hh);
                __nv_bfloat162 ll = __floats2bfloat162_rn(x0 - ff.x, x1 - ff.y);
                pH[q] = *(uint32_t*)&hh;
                pL[q] = *(uint32_t*)&ll;
            }
            #pragma unroll
            for (int np = 0; np < 4; np++) {
                uint32_t va = ((ks * 16 + vb_row) * AT_STRIDE + np * 16 + vb_col) * 2;
                uint32_t vh[4], vl[4];
                LDSM_X4_T(vh[0], vh[1], vh[2], vh[3], Vh_b + va);
                LDSM_X4_T(vl[0], vl[1], vl[2], vl[3], Vl_b + va);
                mma_bf16(ofrag[2*np],   pH, &vh[0]);
                mma_bf16(ofrag[2*np],   pH, &vl[0]);
                mma_bf16(ofrag[2*np],   pL, &vh[0]);
                mma_bf16(ofrag[2*np+1], pH, &vh[2]);
                mma_bf16(ofrag[2*np+1], pH, &vl[2]);
                mma_bf16(ofrag[2*np+1], pL, &vh[2]);
            }
        }
    }

    // ---- epilogue ----
    const float inv0 = 1.f / l_i[0], inv1 = 1.f / l_i[1];
    const int row0 = q0 + wq + (lane >> 2);
    const size_t obase = (size_t)(b * TLEN + row0) * CD + h * DH;
    #pragma unroll
    for (int nt = 0; nt < 8; nt++) {
        int col = nt * 8 + (lane & 3) * 2;
        *(float2*)(y + obase + col) =
            make_float2(ofrag[nt][0] * inv0, ofrag[nt][1] * inv0);
        *(float2*)(y + obase + (size_t)8 * CD + col) =
            make_float2(ofrag[nt][2] * inv1, ofrag[nt][3] * inv1);
    }
}

// ---------------------------------------------------------------------------
extern "C" void kernel_launch(void* const* d_in, const int* in_sizes, int n_in,
                              void* d_out, int out_size)
{
    const float* x      = (const float*)d_in[0];
    const float* W_attn = (const float*)d_in[1];
    const float* b_attn = (const float*)d_in[2];
    const float* W_proj = (const float*)d_in[3];
    const float* b_proj = (const float*)d_in[4];
    float* out = (float*)d_out;

    float *qkv = nullptr, *yb = nullptr;
    cudaGetSymbolAddress((void**)&qkv, g_qkv);
    cudaGetSymbolAddress((void**)&yb,  g_y);

    const int smem_attn = 6 * 64 * AT_STRIDE * (int)sizeof(__nv_bfloat16);  // 55296
    cudaFuncSetAttribute(attn_mma,
                         cudaFuncAttributeMaxDynamicSharedMemorySize, smem_attn);

    // 1) qkv = x @ W_attn + b_attn   [4096, 3072]
    dim3 g1(C3 / 128, BT / 128);
    gemm_mma<<<g1, 256>>>(x, W_attn, b_attn, qkv, C3, CD);

    // 2) causal flash attention -> y [4096, 1024]
    dim3 g2(TLEN / 64, NH, 2);
    attn_mma<<<g2, 128, smem_attn>>>(qkv, yb);

    // 3) out = y @ W_proj + b_proj   [4096, 1024]
    dim3 g3(CD / 128, BT / 128);
    gemm_mma<<<g3, 256>>>(yb, W_proj, b_proj, out, CD, CD);
}